// round 8
// baseline (speedup 1.0000x reference)
#include <cuda_runtime.h>
#include <cuda_bf16.h>

// BERTLatticeEmbedding: ragged segment mean-pool.
// hidden [B,S,H] f32, word_ids [B,S] int32 (sorted per row),
// out [B,T,H] f32. B=64, S=512, H=768, T=400.
//
// R5:
//  K1: block per sample; word_ids row in SMEM; 401 LDS binary searches ->
//      g_start[b][0..T] (lower_bound table, g_start[b][T] = S).
//  K2: warp-task = (b, 4-word group, half-row). 5 boundaries fetched by 5
//      lanes in one coalesced load, shfl-broadcast. Pieces of the 4 words are
//      one contiguous range: streamed with 1-piece register prefetch.

#define B_DIM 64
#define S_DIM 512
#define H_DIM 768
#define T_DIM 400
#define H4    (H_DIM / 4)     // 192 float4 per row
#define HALF4 (H4 / 2)        // 96 float4 per half-row
#define WGRP  4               // words per warp task
#define TPB   256
#define TASKS_PER_B (2 * T_DIM / WGRP)   // 200

__device__ int g_start[B_DIM * (T_DIM + 1)];

__global__ __launch_bounds__(512) void bounds_kernel(
    const int* __restrict__ word_ids)
{
    __shared__ int s_row[S_DIM];
    const int b   = blockIdx.x;
    const int tid = threadIdx.x;

    s_row[tid] = word_ids[b * S_DIM + tid];
    __syncthreads();

    if (tid <= T_DIM) {
        int lo = 0, hi = S_DIM;
        while (lo < hi) {
            int mid = (lo + hi) >> 1;
            if (s_row[mid] < tid) lo = mid + 1; else hi = mid;
        }
        g_start[b * (T_DIM + 1) + tid] = lo;
    }
}

__device__ __forceinline__ void f4add(float4& a, const float4 v) {
    a.x += v.x; a.y += v.y; a.z += v.z; a.w += v.w;
}
__device__ __forceinline__ void f4scale(float4& a, const float s) {
    a.x *= s; a.y *= s; a.z *= s; a.w *= s;
}

__global__ __launch_bounds__(TPB) void pool_kernel(
    const float* __restrict__ hidden,
    float* __restrict__ out)
{
    const int warp = threadIdx.x >> 5;
    const int lane = threadIdx.x & 31;
    const int task = blockIdx.x * (TPB / 32) + warp;   // 0 .. B*200-1
    const int b    = task / TASKS_PER_B;
    const int rem  = task - b * TASKS_PER_B;
    const int wg   = rem >> 1;                         // word group 0..99
    const int half = rem & 1;
    const int w0   = wg * WGRP;
    const int off  = half * HALF4 + lane;

    // 5 boundaries via one coalesced load + shfl.
    const int* __restrict__ stp = g_start + b * (T_DIM + 1) + w0;
    const int myb = __ldg(stp + (lane < WGRP ? lane : WGRP));
    const unsigned FULL = 0xffffffffu;
    const int sBeg = __shfl_sync(FULL, myb, 0);
    const int sEnd = __shfl_sync(FULL, myb, WGRP);

    const float4* __restrict__ hin =
        reinterpret_cast<const float4*>(hidden + (size_t)b * S_DIM * H_DIM) + off;
    float4* __restrict__ outBase =
        reinterpret_cast<float4*>(out + ((size_t)b * T_DIM + w0) * H_DIM) + off;

    const float4 Z = make_float4(0.f, 0.f, 0.f, 0.f);

    int wi = 0;
    int segStart = sBeg;
    int curEnd   = __shfl_sync(FULL, myb, 1);

    // Leading / fully-empty words.
    while (wi < WGRP && curEnd == segStart) {
        float4* op = outBase + (size_t)wi * H4;
        __stcs(op, Z); __stcs(op + 32, Z); __stcs(op + 64, Z);
        ++wi;
        if (wi < WGRP) curEnd = __shfl_sync(FULL, myb, wi + 1);
    }

    float4 a0 = Z, a1 = Z, a2 = Z;
    float4 v0, v1, v2;
    if (sBeg < sEnd) {
        const float4* p = hin + (size_t)sBeg * H4;
        v0 = __ldcs(p); v1 = __ldcs(p + 32); v2 = __ldcs(p + 64);
    }

    for (int s = sBeg; s < sEnd; ++s) {
        float4 u0, u1, u2;
        if (s + 1 < sEnd) {
            const float4* p = hin + (size_t)(s + 1) * H4;
            u0 = __ldcs(p); u1 = __ldcs(p + 32); u2 = __ldcs(p + 64);
        }
        f4add(a0, v0); f4add(a1, v1); f4add(a2, v2);

        if (s + 1 == curEnd) {                 // word wi complete
            const float inv = 1.0f / (float)(s + 1 - segStart);
            f4scale(a0, inv); f4scale(a1, inv); f4scale(a2, inv);
            float4* op = outBase + (size_t)wi * H4;
            __stcs(op, a0); __stcs(op + 32, a1); __stcs(op + 64, a2);
            a0 = Z; a1 = Z; a2 = Z;
            segStart = s + 1;
            ++wi;
            if (wi < WGRP) {
                curEnd = __shfl_sync(FULL, myb, wi + 1);
                while (curEnd == segStart && wi < WGRP) {   // empty words
                    float4* op2 = outBase + (size_t)wi * H4;
                    __stcs(op2, Z); __stcs(op2 + 32, Z); __stcs(op2 + 64, Z);
                    ++wi;
                    if (wi < WGRP) curEnd = __shfl_sync(FULL, myb, wi + 1);
                }
            }
        }
        v0 = u0; v1 = u1; v2 = u2;
    }
}

extern "C" void kernel_launch(void* const* d_in, const int* in_sizes, int n_in,
                              void* d_out, int out_size)
{
    const float* hidden   = (const float*)d_in[0];
    const int*   word_ids = (const int*)d_in[1];
    float* out = (float*)d_out;

    bounds_kernel<<<B_DIM, 512>>>(word_ids);

    const int total_tasks = B_DIM * TASKS_PER_B;          // 12800 warps
    pool_kernel<<<total_tasks / (TPB / 32), TPB>>>(hidden, out);
}

// round 9
// speedup vs baseline: 1.1319x; 1.1319x over previous
#include <cuda_runtime.h>
#include <cuda_bf16.h>

// BERTLatticeEmbedding: ragged segment mean-pool.
// hidden [B,S,H] f32, word_ids [B,S] int32 (sorted per row),
// out [B,T,H] f32. B=64, S=512, H=768, T=400.
//
// R6: K1 builds lower_bound table g_start[b][0..T] (LDS binary searches).
//     K2: flat warp-task = (b, word-pair, half-row). 3 boundaries via one
//     coalesced load + shfl; both words' pieces are one contiguous range,
//     accumulated with an unroll-2 loop and warp-uniform predicated adds
//     into A/B accumulators. Always-store (zeros handled by acc=0,inv=1).

#define B_DIM 64
#define S_DIM 512
#define H_DIM 768
#define T_DIM 400
#define H4    (H_DIM / 4)     // 192 float4 per row
#define HALF4 (H4 / 2)        // 96 float4 per half-row
#define TPB   256
#define TASKS_PER_B (T_DIM)   // 200 pairs * 2 halves = 400

__device__ int g_start[B_DIM * (T_DIM + 1)];

__global__ __launch_bounds__(512) void bounds_kernel(
    const int* __restrict__ word_ids)
{
    __shared__ int s_row[S_DIM];
    const int b   = blockIdx.x;
    const int tid = threadIdx.x;

    s_row[tid] = word_ids[b * S_DIM + tid];
    __syncthreads();

    if (tid <= T_DIM) {
        int lo = 0, hi = S_DIM;
        while (lo < hi) {
            int mid = (lo + hi) >> 1;
            if (s_row[mid] < tid) lo = mid + 1; else hi = mid;
        }
        g_start[b * (T_DIM + 1) + tid] = lo;
    }
}

__device__ __forceinline__ void f4add(float4& a, const float4 v) {
    a.x += v.x; a.y += v.y; a.z += v.z; a.w += v.w;
}
__device__ __forceinline__ void f4scale(float4& a, const float s) {
    a.x *= s; a.y *= s; a.z *= s; a.w *= s;
}

__global__ __launch_bounds__(TPB) void pool_kernel(
    const float* __restrict__ hidden,
    float* __restrict__ out)
{
    const int warp = threadIdx.x >> 5;
    const int lane = threadIdx.x & 31;
    const int task = blockIdx.x * (TPB / 32) + warp;  // 0 .. B*400-1
    const int b    = task / TASKS_PER_B;
    const int rem  = task - b * TASKS_PER_B;
    const int wp   = rem >> 1;                        // word pair 0..199
    const int half = rem & 1;
    const int w0   = wp * 2;
    const int off  = half * HALF4 + lane;

    // Boundaries start[w0], start[w0+1], start[w0+2]: one coalesced load + shfl.
    const int* __restrict__ stp = g_start + b * (T_DIM + 1) + w0;
    const int myb = __ldg(stp + (lane < 2 ? lane : 2));
    const unsigned FULL = 0xffffffffu;
    const int s0 = __shfl_sync(FULL, myb, 0);
    const int s1 = __shfl_sync(FULL, myb, 1);
    const int s2 = __shfl_sync(FULL, myb, 2);

    const float4* __restrict__ hin =
        reinterpret_cast<const float4*>(hidden + (size_t)b * S_DIM * H_DIM) + off;

    const float4 Z = make_float4(0.f, 0.f, 0.f, 0.f);
    float4 A0 = Z, A1 = Z, A2 = Z;   // word w0
    float4 B0 = Z, B1 = Z, B2 = Z;   // word w0+1

    // Contiguous combined range [s0, s2); warp-uniform predicates.
    for (int s = s0; s < s2; s += 2) {
        const float4* q = hin + (size_t)s * H4;
        const bool has1 = (s + 1 < s2);
        float4 v0 = __ldcs(q);
        float4 v1 = __ldcs(q + 32);
        float4 v2 = __ldcs(q + 64);
        float4 u0, u1, u2;
        if (has1) {
            u0 = __ldcs(q + H4);
            u1 = __ldcs(q + H4 + 32);
            u2 = __ldcs(q + H4 + 64);
        }
        if (s < s1) { f4add(A0, v0); f4add(A1, v1); f4add(A2, v2); }
        else        { f4add(B0, v0); f4add(B1, v1); f4add(B2, v2); }
        if (has1) {
            if (s + 1 < s1) { f4add(A0, u0); f4add(A1, u1); f4add(A2, u2); }
            else            { f4add(B0, u0); f4add(B1, u1); f4add(B2, u2); }
        }
    }

    const int c0 = s1 - s0;
    const int c1 = s2 - s1;
    const float invA = 1.0f / (float)(c0 > 0 ? c0 : 1);
    const float invB = 1.0f / (float)(c1 > 0 ? c1 : 1);
    f4scale(A0, invA); f4scale(A1, invA); f4scale(A2, invA);
    f4scale(B0, invB); f4scale(B1, invB); f4scale(B2, invB);

    float4* __restrict__ opA =
        reinterpret_cast<float4*>(out + ((size_t)b * T_DIM + w0) * H_DIM) + off;
    float4* __restrict__ opB = opA + H4;
    __stcs(opA,      A0);
    __stcs(opA + 32, A1);
    __stcs(opA + 64, A2);
    __stcs(opB,      B0);
    __stcs(opB + 32, B1);
    __stcs(opB + 64, B2);
}

extern "C" void kernel_launch(void* const* d_in, const int* in_sizes, int n_in,
                              void* d_out, int out_size)
{
    const float* hidden   = (const float*)d_in[0];
    const int*   word_ids = (const int*)d_in[1];
    float* out = (float*)d_out;

    bounds_kernel<<<B_DIM, 512>>>(word_ids);

    const int total_tasks = B_DIM * TASKS_PER_B;        // 25600 warp-tasks
    pool_kernel<<<total_tasks / (TPB / 32), TPB>>>(hidden, out);
}